// round 12
// baseline (speedup 1.0000x reference)
#include <cuda_runtime.h>
#include <cuda_bf16.h>
#include <cstdint>

#define NN   100000
#define NE   1600000
#define D    128
#define DOUT 64
#define MT   128
#define NBLK ((NN + MT - 1) / MT)     // 782
#define SCANB ((NN + 255) / 256)      // 391

// ---------------- scratch ----------------
__device__ __align__(16) float g_bufA[NN * D];
__device__ __align__(16) uint32_t g_hi[NN * (D / 2)];
__device__ __align__(16) uint32_t g_lo[NN * (D / 2)];
__device__ __align__(16) float g_stats2[4 * 256];  // per-stats-GEMM: [sum(128), sumsq(128)]
__device__ int g_is64;
__device__ int g_deg[NN];
__device__ int g_off[NN];
__device__ int g_cur[NN];
__device__ int g_csr[NE];
__device__ int g_bsum[512];
__device__ __align__(16) __nv_bfloat16 g_wh[8 * D * D];
__device__ __align__(16) __nv_bfloat16 g_wl[8 * D * D];

__device__ __forceinline__ uint32_t pack2(__nv_bfloat16 a, __nv_bfloat16 b) {
    return (uint32_t)__bfloat16_as_ushort(a) | ((uint32_t)__bfloat16_as_ushort(b) << 16);
}
__device__ __forceinline__ void split2(float x, float y, uint32_t& h, uint32_t& l) {
    __nv_bfloat16 hx = __float2bfloat16(x), hy = __float2bfloat16(y);
    h = pack2(hx, hy);
    l = pack2(__float2bfloat16(x - __bfloat162float(hx)),
              __float2bfloat16(y - __bfloat162float(hy)));
}
// reconstruct two fp32 values from packed hi/lo bf16 pairs
__device__ __forceinline__ float2 unsplit2(uint32_t h, uint32_t l) {
    float2 r;
    r.x = __bfloat162float(__ushort_as_bfloat16((unsigned short)(h & 0xFFFFu))) +
          __bfloat162float(__ushort_as_bfloat16((unsigned short)(l & 0xFFFFu)));
    r.y = __bfloat162float(__ushort_as_bfloat16((unsigned short)(h >> 16))) +
          __bfloat162float(__ushort_as_bfloat16((unsigned short)(l >> 16)));
    return r;
}

#define MMA_BF16(c, a, b0_, b1_) \
    asm volatile("mma.sync.aligned.m16n8k16.row.col.f32.bf16.bf16.f32 " \
        "{%0,%1,%2,%3}, {%4,%5,%6,%7}, {%8,%9}, {%0,%1,%2,%3};" \
        : "+f"((c)[0]), "+f"((c)[1]), "+f"((c)[2]), "+f"((c)[3]) \
        : "r"((a)[0]), "r"((a)[1]), "r"((a)[2]), "r"((a)[3]), "r"(b0_), "r"(b1_))

// ---------------- init: zero deg + detect dtype + zero stats slots ----------------
__global__ void init_kernel(const void* ei) {
    if (blockIdx.x < SCANB) {
        int i = blockIdx.x * 256 + threadIdx.x;
        if (i < NN) g_deg[i] = 0;
    } else {
        const long long* p = (const long long*)ei;
        long long v = p[threadIdx.x];
        int ok = (v >= 0 && v < NN);
        ok = __syncthreads_and(ok);
        if (threadIdx.x == 0) g_is64 = ok;
        ((float4*)g_stats2)[threadIdx.x] = make_float4(0.f, 0.f, 0.f, 0.f);
    }
}

// transpose + bf16-split all 8 weight matrices: g_wh/g_wl[m][n][k]
__global__ void prep_w(const float* __restrict__ W1, const float* __restrict__ W2,
                       const float* __restrict__ fW1, const float* __restrict__ fW2) {
    int m = blockIdx.y;
    const float* src;
    int ncols;
    if (m < 3)       { src = W1 + m * D * D;       ncols = D; }
    else if (m < 6)  { src = W2 + (m - 3) * D * D; ncols = D; }
    else if (m == 6) { src = fW1;                  ncols = D; }
    else             { src = fW2;                  ncols = DOUT; }
    int idx = blockIdx.x * 256 + threadIdx.x;
    if (idx >= ncols * D) return;
    int n = idx / D, k = idx % D;
    float v = __ldg(src + k * ncols + n);
    __nv_bfloat16 h = __float2bfloat16(v);
    g_wh[m * D * D + idx] = h;
    g_wl[m * D * D + idx] = __float2bfloat16(v - __bfloat162float(h));
}

__global__ void hist_kernel(const void* ei) {
    int e = blockIdx.x * 256 + threadIdx.x;
    if (e >= NE) return;
    int d = g_is64 ? (int)((const long long*)ei)[NE + e] : ((const int*)ei)[NE + e];
    atomicAdd(&g_deg[d], 1);
}
__global__ void scan1_kernel() {
    __shared__ int s[256];
    int i = blockIdx.x * 256 + threadIdx.x;
    int v = (i < NN) ? g_deg[i] : 0;
    s[threadIdx.x] = v;
    __syncthreads();
    for (int o = 1; o < 256; o <<= 1) {
        int t = (threadIdx.x >= o) ? s[threadIdx.x - o] : 0;
        __syncthreads();
        s[threadIdx.x] += t;
        __syncthreads();
    }
    if (i < NN) g_off[i] = s[threadIdx.x];
    if (threadIdx.x == 255) g_bsum[blockIdx.x] = s[255];
}
__global__ void scan2_kernel() {
    __shared__ int s[512];
    int v = (threadIdx.x < SCANB) ? g_bsum[threadIdx.x] : 0;
    s[threadIdx.x] = v;
    __syncthreads();
    for (int o = 1; o < 512; o <<= 1) {
        int t = (threadIdx.x >= o) ? s[threadIdx.x - o] : 0;
        __syncthreads();
        s[threadIdx.x] += t;
        __syncthreads();
    }
    g_bsum[threadIdx.x] = s[threadIdx.x] - v;
}
__global__ void scan3_kernel() {
    int i = blockIdx.x * 256 + threadIdx.x;
    if (i >= NN) return;
    int e = g_off[i] - g_deg[i] + g_bsum[blockIdx.x];
    g_off[i] = e;
    g_cur[i] = e;
}
__global__ void fill_kernel(const void* ei) {
    int e = blockIdx.x * 256 + threadIdx.x;
    if (e >= NE) return;
    int s, d;
    if (g_is64) { const long long* p = (const long long*)ei; s = (int)p[e]; d = (int)p[NE + e]; }
    else        { const int* p = (const int*)ei;             s = p[e];      d = p[NE + e]; }
    int pos = atomicAdd(&g_cur[d], 1);
    g_csr[pos] = s;
}

// gather h[w] = x[w] + sum_j x[csr[j]]  -> bf16 hi/lo split, one warp per node
__global__ __launch_bounds__(256)
void gather_bf16_kernel(const float* __restrict__ x,
                        uint32_t* __restrict__ hi, uint32_t* __restrict__ lo) {
    int w = (blockIdx.x * 256 + threadIdx.x) >> 5;
    int lane = threadIdx.x & 31;
    if (w >= NN) return;
    const float4* xb = (const float4*)x;
    float4 acc = __ldg(xb + (size_t)w * 32 + lane);
    int i = g_off[w];
    int end = i + g_deg[w];
    for (; i + 4 <= end; i += 4) {
        int s0 = __ldg(g_csr + i),     s1 = __ldg(g_csr + i + 1);
        int s2 = __ldg(g_csr + i + 2), s3 = __ldg(g_csr + i + 3);
        float4 v0 = __ldg(xb + (size_t)s0 * 32 + lane);
        float4 v1 = __ldg(xb + (size_t)s1 * 32 + lane);
        float4 v2 = __ldg(xb + (size_t)s2 * 32 + lane);
        float4 v3 = __ldg(xb + (size_t)s3 * 32 + lane);
        acc.x += (v0.x + v1.x) + (v2.x + v3.x);
        acc.y += (v0.y + v1.y) + (v2.y + v3.y);
        acc.z += (v0.z + v1.z) + (v2.z + v3.z);
        acc.w += (v0.w + v1.w) + (v2.w + v3.w);
    }
    for (; i < end; ++i) {
        int s = __ldg(g_csr + i);
        float4 v = __ldg(xb + (size_t)s * 32 + lane);
        acc.x += v.x; acc.y += v.y; acc.z += v.z; acc.w += v.w;
    }
    uint32_t h0, l0, h1, l1;
    split2(acc.x, acc.y, h0, l0);
    split2(acc.z, acc.w, h1, l1);
    ((uint2*)hi)[(size_t)w * 32 + lane] = make_uint2(h0, h1);
    ((uint2*)lo)[(size_t)w * 32 + lane] = make_uint2(l0, l1);
}

// conv: hi/lo -> reconstruct -> BN+ReLU -> re-split, IN PLACE; scale/shift per-block
__global__ __launch_bounds__(256)
void conv_bn_inplace_kernel(uint32_t* __restrict__ hi, uint32_t* __restrict__ lo,
                            const float* __restrict__ stats,
                            const float* __restrict__ gamma,
                            const float* __restrict__ beta) {
    __shared__ float sc_s[128], sh_s[128];
    int tid = threadIdx.x;
    if (tid < 128) {
        float mu  = stats[tid] * (1.0f / NN);
        float var = stats[128 + tid] * (1.0f / NN) - mu * mu;
        float sc  = __ldg(gamma + tid) * rsqrtf(var + 1e-5f);
        sc_s[tid] = sc;
        sh_s[tid] = __ldg(beta + tid) - mu * sc;
    }
    __syncthreads();
    int i = blockIdx.x * 256 + tid;
    if (i >= NN * 32) return;
    uint2 hv = ((const uint2*)hi)[i];
    uint2 lv = ((const uint2*)lo)[i];
    float2 a = unsplit2(hv.x, lv.x);
    float2 b = unsplit2(hv.y, lv.y);
    int k = (i & 31) * 4;
    float4 sc = *(const float4*)(sc_s + k);
    float4 sh = *(const float4*)(sh_s + k);
    a.x = fmaxf(fmaf(a.x, sc.x, sh.x), 0.f);
    a.y = fmaxf(fmaf(a.y, sc.y, sh.y), 0.f);
    b.x = fmaxf(fmaf(b.x, sc.z, sh.z), 0.f);
    b.y = fmaxf(fmaf(b.y, sc.w, sh.w), 0.f);
    uint32_t h0, l0, h1, l1;
    split2(a.x, a.y, h0, l0);
    split2(b.x, b.y, h1, l1);
    ((uint2*)hi)[i] = make_uint2(h0, h1);
    ((uint2*)lo)[i] = make_uint2(l0, l1);
}

// ---------------- HMMA GEMM: Out = split(A) @ Wt^T + bias ----------------
// STATS: fused column sum/sumsq of Out into stats[0:256) (shfl-reduced epilogue).
// EMIT:  0 = store fp32 Out; 1 = store bf16 hi/lo split (Ohi/Olo), in-place safe
//        (guarded by a block-wide sync after the mainloop).
template <int NOUT, bool RELU, bool STATS, int EMIT>
__global__ __launch_bounds__(256, 2)
void mma_gemm(const uint32_t* __restrict__ Ahi, const uint32_t* __restrict__ Alo,
              const uint32_t* __restrict__ Wh, const uint32_t* __restrict__ Wl,
              const float* __restrict__ bias, float* __restrict__ Out,
              uint32_t* __restrict__ Ohi, uint32_t* __restrict__ Olo,
              float* __restrict__ stats) {
    constexpr int WM = (NOUT == 128) ? 4 : 8;   // warps along m
    constexpr int MF = 128 / (WM * 16);         // m16 frags per warp
    constexpr int RS = 68;                      // smem row stride (u32), pad for banks
    extern __shared__ uint32_t ws[];
    uint32_t* wh_s = ws;
    uint32_t* wl_s = ws + NOUT * RS;
    __shared__ float ssum[128], ssq[128];

    int tid = threadIdx.x;
    for (int i = tid; i < NOUT * 64; i += 256) {
        int n = i >> 6, kw = i & 63;
        wh_s[n * RS + kw] = __ldg(Wh + i);
        wl_s[n * RS + kw] = __ldg(Wl + i);
    }
    if (STATS && tid < 128) { ssum[tid] = 0.f; ssq[tid] = 0.f; }
    __syncthreads();

    int wid = tid >> 5, lane = tid & 31;
    int g = lane >> 2, tig = lane & 3;
    int mwid = wid % WM, nwid = wid / WM;
    int n0 = nwid * 64;
    int mbase = blockIdx.x * MT + mwid * (MF * 16);

    float acc[MF][8][4];
#pragma unroll
    for (int mf = 0; mf < MF; ++mf)
#pragma unroll
        for (int nf = 0; nf < 8; ++nf)
#pragma unroll
            for (int c = 0; c < 4; ++c) acc[mf][nf][c] = 0.f;

    for (int ks = 0; ks < 8; ++ks) {
        uint32_t ah[MF][4], al[MF][4];
#pragma unroll
        for (int mf = 0; mf < MF; ++mf) {
            int r0 = mbase + mf * 16 + g;
            int r1 = r0 + 8;
            int o = ks * 8 + tig;
            bool v0 = r0 < NN, v1 = r1 < NN;
            size_t p0 = (size_t)r0 * 64 + o, p1 = (size_t)r1 * 64 + o;
            ah[mf][0] = v0 ? __ldg(Ahi + p0) : 0u;
            ah[mf][1] = v1 ? __ldg(Ahi + p1) : 0u;
            ah[mf][2] = v0 ? __ldg(Ahi + p0 + 4) : 0u;
            ah[mf][3] = v1 ? __ldg(Ahi + p1 + 4) : 0u;
            al[mf][0] = v0 ? __ldg(Alo + p0) : 0u;
            al[mf][1] = v1 ? __ldg(Alo + p1) : 0u;
            al[mf][2] = v0 ? __ldg(Alo + p0 + 4) : 0u;
            al[mf][3] = v1 ? __ldg(Alo + p1 + 4) : 0u;
        }
#pragma unroll
        for (int nf = 0; nf < 8; ++nf) {
            int bo = (n0 + nf * 8 + g) * RS + ks * 8 + tig;
            uint32_t bh0 = wh_s[bo], bh1 = wh_s[bo + 4];
            uint32_t bl0 = wl_s[bo], bl1 = wl_s[bo + 4];
#pragma unroll
            for (int mf = 0; mf < MF; ++mf) {
                MMA_BF16(acc[mf][nf], ah[mf], bh0, bh1);
                MMA_BF16(acc[mf][nf], al[mf], bh0, bh1);
                MMA_BF16(acc[mf][nf], ah[mf], bl0, bl1);
            }
        }
    }

    // EMIT writes alias the A buffers: wait until ALL warps finished reading A.
    if (EMIT) __syncthreads();

#pragma unroll
    for (int nf = 0; nf < 8; ++nf) {
        int col = n0 + nf * 8 + tig * 2;
        float2 b = *(const float2*)(bias + col);
        float s0 = 0.f, s1 = 0.f, q0 = 0.f, q1 = 0.f;
#pragma unroll
        for (int mf = 0; mf < MF; ++mf) {
            int r0 = mbase + mf * 16 + g;
            int r1 = r0 + 8;
            float c0 = acc[mf][nf][0] + b.x, c1 = acc[mf][nf][1] + b.y;
            float c2 = acc[mf][nf][2] + b.x, c3 = acc[mf][nf][3] + b.y;
            if (RELU) {
                c0 = fmaxf(c0, 0.f); c1 = fmaxf(c1, 0.f);
                c2 = fmaxf(c2, 0.f); c3 = fmaxf(c3, 0.f);
            }
            if (r0 < NN) {
                if (EMIT) {
                    uint32_t hh, ll;
                    split2(c0, c1, hh, ll);
                    Ohi[(size_t)r0 * 64 + col / 2] = hh;
                    Olo[(size_t)r0 * 64 + col / 2] = ll;
                } else {
                    *(float2*)(Out + (size_t)r0 * NOUT + col) = make_float2(c0, c1);
                }
                if (STATS) { s0 += c0; s1 += c1; q0 += c0 * c0; q1 += c1 * c1; }
            }
            if (r1 < NN) {
                if (EMIT) {
                    uint32_t hh, ll;
                    split2(c2, c3, hh, ll);
                    Ohi[(size_t)r1 * 64 + col / 2] = hh;
                    Olo[(size_t)r1 * 64 + col / 2] = ll;
                } else {
                    *(float2*)(Out + (size_t)r1 * NOUT + col) = make_float2(c2, c3);
                }
                if (STATS) { s0 += c2; s1 += c3; q0 += c2 * c2; q1 += c3 * c3; }
            }
        }
        if (STATS) {
#pragma unroll
            for (int o = 4; o < 32; o <<= 1) {
                s0 += __shfl_xor_sync(0xFFFFFFFFu, s0, o);
                s1 += __shfl_xor_sync(0xFFFFFFFFu, s1, o);
                q0 += __shfl_xor_sync(0xFFFFFFFFu, q0, o);
                q1 += __shfl_xor_sync(0xFFFFFFFFu, q1, o);
            }
            if (lane < 4) {
                atomicAdd(&ssum[col], s0);
                atomicAdd(&ssum[col + 1], s1);
                atomicAdd(&ssq[col], q0);
                atomicAdd(&ssq[col + 1], q1);
            }
        }
    }
    if (STATS) {
        __syncthreads();
        if (tid < 128) {
            atomicAdd(&stats[tid], ssum[tid]);
            atomicAdd(&stats[128 + tid], ssq[tid]);
        }
    }
}

// ---------------- host ----------------
extern "C" void kernel_launch(void* const* d_in, const int* in_sizes, int n_in,
                              void* d_out, int out_size) {
    const float* x    = (const float*)d_in[0];
    const void*  ei   = d_in[1];
    const float* W1   = (const float*)d_in[2];
    const float* b1   = (const float*)d_in[3];
    const float* g1   = (const float*)d_in[4];
    const float* be1  = (const float*)d_in[5];
    const float* W2   = (const float*)d_in[6];
    const float* b2   = (const float*)d_in[7];
    const float* fW1  = (const float*)d_in[8];
    const float* fb1  = (const float*)d_in[9];
    const float* fg1  = (const float*)d_in[10];
    const float* fbe1 = (const float*)d_in[11];
    const float* fW2  = (const float*)d_in[12];
    const float* fb2  = (const float*)d_in[13];
    float* out = (float*)d_out;

    float *A, *st;
    uint32_t *hi, *lo, *wh, *wl;
    cudaGetSymbolAddress((void**)&A, g_bufA);
    cudaGetSymbolAddress((void**)&st, g_stats2);
    cudaGetSymbolAddress((void**)&hi, g_hi);
    cudaGetSymbolAddress((void**)&lo, g_lo);
    cudaGetSymbolAddress((void**)&wh, g_wh);
    cudaGetSymbolAddress((void**)&wl, g_wl);

    const int SMA = 128 * 68 * 4 * 2;   // 69632 B
    const int SMB = 64 * 68 * 4 * 2;    // 34816 B
    cudaFuncSetAttribute(mma_gemm<128, false, true, 1>,
                         cudaFuncAttributeMaxDynamicSharedMemorySize, SMA);
    cudaFuncSetAttribute(mma_gemm<128, true, false, 0>,
                         cudaFuncAttributeMaxDynamicSharedMemorySize, SMA);
    cudaFuncSetAttribute(mma_gemm<128, true, false, 1>,
                         cudaFuncAttributeMaxDynamicSharedMemorySize, SMA);
    cudaFuncSetAttribute(mma_gemm<64, false, false, 0>,
                         cudaFuncAttributeMaxDynamicSharedMemorySize, SMB);

    init_kernel<<<SCANB + 1, 256>>>(ei);
    prep_w<<<dim3(64, 8), 256>>>(W1, W2, fW1, fW2);
    hist_kernel<<<NE / 256, 256>>>(ei);
    scan1_kernel<<<SCANB, 256>>>();
    scan2_kernel<<<1, 512>>>();
    scan3_kernel<<<SCANB, 256>>>();
    fill_kernel<<<NE / 256, 256>>>(ei);

    const int gblocks = (NN * 32 + 255) / 256;   // 12500
    const int cblocks = (NN * 32 + 255) / 256;

    const float* cur = x;
    for (int l = 0; l < 3; ++l) {
        float* slot = st + l * 256;
        gather_bf16_kernel<<<gblocks, 256>>>(cur, hi, lo);
        // GEMM1: stats + emit hi/lo split in place (no fp32 C buffer)
        mma_gemm<128, false, true, 1><<<NBLK, 256, SMA>>>(
            hi, lo, wh + (size_t)l * D * 64, wl + (size_t)l * D * 64, b1 + l * D,
            nullptr, hi, lo, slot);
        conv_bn_inplace_kernel<<<cblocks, 256>>>(hi, lo, slot, g1 + l * D, be1 + l * D);
        if (l < 2) {
            mma_gemm<128, true, false, 0><<<NBLK, 256, SMA>>>(
                hi, lo, wh + (size_t)(3 + l) * D * 64, wl + (size_t)(3 + l) * D * 64,
                b2 + l * D, A, nullptr, nullptr, nullptr);
            cur = A;
        } else {
            // layer-3 GEMM2: emit hi/lo in place (next stage is the final MLP GEMM)
            mma_gemm<128, true, false, 1><<<NBLK, 256, SMA>>>(
                hi, lo, wh + (size_t)(3 + l) * D * 64, wl + (size_t)(3 + l) * D * 64,
                b2 + l * D, nullptr, hi, lo, nullptr);
        }
    }
    // final MLP
    mma_gemm<128, false, true, 1><<<NBLK, 256, SMA>>>(
        hi, lo, wh + (size_t)6 * D * 64, wl + (size_t)6 * D * 64, fb1,
        nullptr, hi, lo, st + 3 * 256);
    conv_bn_inplace_kernel<<<cblocks, 256>>>(hi, lo, st + 3 * 256, fg1, fbe1);
    mma_gemm<64, false, false, 0><<<NBLK, 256, SMB>>>(
        hi, lo, wh + (size_t)7 * D * 64, wl + (size_t)7 * D * 64, fb2, out,
        nullptr, nullptr, nullptr);
}

// round 13
// speedup vs baseline: 1.0434x; 1.0434x over previous
#include <cuda_runtime.h>
#include <cuda_bf16.h>
#include <cstdint>

#define NN   100000
#define NE   1600000
#define D    128
#define DOUT 64
#define MT   128
#define NBLK ((NN + MT - 1) / MT)     // 782
#define SCANB ((NN + 255) / 256)      // 391

// ---------------- scratch ----------------
__device__ __align__(16) float g_bufA[NN * D];
__device__ __align__(16) float g_bufC[NN * D];
__device__ __align__(16) uint32_t g_hi[NN * (D / 2)];
__device__ __align__(16) uint32_t g_lo[NN * (D / 2)];
__device__ __align__(16) float g_stats2[4 * 256];  // per-stats-GEMM: [sum(128), sumsq(128)]
__device__ int g_is64;
__device__ int g_deg[NN];
__device__ int g_off[NN];
__device__ int g_cur[NN];
__device__ int g_csr[NE];
__device__ int g_bsum[512];
__device__ __align__(16) __nv_bfloat16 g_wh[8 * D * D];
__device__ __align__(16) __nv_bfloat16 g_wl[8 * D * D];

__device__ __forceinline__ uint32_t pack2(__nv_bfloat16 a, __nv_bfloat16 b) {
    return (uint32_t)__bfloat16_as_ushort(a) | ((uint32_t)__bfloat16_as_ushort(b) << 16);
}
__device__ __forceinline__ void split2(float x, float y, uint32_t& h, uint32_t& l) {
    __nv_bfloat16 hx = __float2bfloat16(x), hy = __float2bfloat16(y);
    h = pack2(hx, hy);
    l = pack2(__float2bfloat16(x - __bfloat162float(hx)),
              __float2bfloat16(y - __bfloat162float(hy)));
}

#define MMA_BF16(c, a, b0_, b1_) \
    asm volatile("mma.sync.aligned.m16n8k16.row.col.f32.bf16.bf16.f32 " \
        "{%0,%1,%2,%3}, {%4,%5,%6,%7}, {%8,%9}, {%0,%1,%2,%3};" \
        : "+f"((c)[0]), "+f"((c)[1]), "+f"((c)[2]), "+f"((c)[3]) \
        : "r"((a)[0]), "r"((a)[1]), "r"((a)[2]), "r"((a)[3]), "r"(b0_), "r"(b1_))

// ---------------- init: zero deg + detect dtype + zero stats slots ----------------
__global__ void init_kernel(const void* ei) {
    if (blockIdx.x < SCANB) {
        int i = blockIdx.x * 256 + threadIdx.x;
        if (i < NN) g_deg[i] = 0;
    } else {
        const long long* p = (const long long*)ei;
        long long v = p[threadIdx.x];
        int ok = (v >= 0 && v < NN);
        ok = __syncthreads_and(ok);
        if (threadIdx.x == 0) g_is64 = ok;
        ((float4*)g_stats2)[threadIdx.x] = make_float4(0.f, 0.f, 0.f, 0.f);
    }
}

// transpose + bf16-split all 8 weight matrices: g_wh/g_wl[m][n][k]
__global__ void prep_w(const float* __restrict__ W1, const float* __restrict__ W2,
                       const float* __restrict__ fW1, const float* __restrict__ fW2) {
    int m = blockIdx.y;
    const float* src;
    int ncols;
    if (m < 3)       { src = W1 + m * D * D;       ncols = D; }
    else if (m < 6)  { src = W2 + (m - 3) * D * D; ncols = D; }
    else if (m == 6) { src = fW1;                  ncols = D; }
    else             { src = fW2;                  ncols = DOUT; }
    int idx = blockIdx.x * 256 + threadIdx.x;
    if (idx >= ncols * D) return;
    int n = idx / D, k = idx % D;
    float v = __ldg(src + k * ncols + n);
    __nv_bfloat16 h = __float2bfloat16(v);
    g_wh[m * D * D + idx] = h;
    g_wl[m * D * D + idx] = __float2bfloat16(v - __bfloat162float(h));
}

// histogram of dst, 2 edges per thread (128-bit index loads)
__global__ void hist_kernel(const void* ei) {
    int e = (blockIdx.x * 256 + threadIdx.x) * 2;
    if (e >= NE) return;
    int d0, d1;
    if (g_is64) {
        longlong2 p = __ldg((const longlong2*)((const long long*)ei + NE) + (e >> 1));
        d0 = (int)p.x; d1 = (int)p.y;
    } else {
        int2 p = __ldg((const int2*)((const int*)ei + NE) + (e >> 1));
        d0 = p.x; d1 = p.y;
    }
    atomicAdd(&g_deg[d0], 1);
    atomicAdd(&g_deg[d1], 1);
}
__global__ void scan1_kernel() {
    __shared__ int s[256];
    int i = blockIdx.x * 256 + threadIdx.x;
    int v = (i < NN) ? g_deg[i] : 0;
    s[threadIdx.x] = v;
    __syncthreads();
    for (int o = 1; o < 256; o <<= 1) {
        int t = (threadIdx.x >= o) ? s[threadIdx.x - o] : 0;
        __syncthreads();
        s[threadIdx.x] += t;
        __syncthreads();
    }
    if (i < NN) g_off[i] = s[threadIdx.x];
    if (threadIdx.x == 255) g_bsum[blockIdx.x] = s[255];
}
__global__ void scan2_kernel() {
    __shared__ int s[512];
    int v = (threadIdx.x < SCANB) ? g_bsum[threadIdx.x] : 0;
    s[threadIdx.x] = v;
    __syncthreads();
    for (int o = 1; o < 512; o <<= 1) {
        int t = (threadIdx.x >= o) ? s[threadIdx.x - o] : 0;
        __syncthreads();
        s[threadIdx.x] += t;
        __syncthreads();
    }
    g_bsum[threadIdx.x] = s[threadIdx.x] - v;
}
__global__ void scan3_kernel() {
    int i = blockIdx.x * 256 + threadIdx.x;
    if (i >= NN) return;
    int e = g_off[i] - g_deg[i] + g_bsum[blockIdx.x];
    g_off[i] = e;
    g_cur[i] = e;
}
// CSR fill, 2 edges per thread
__global__ void fill_kernel(const void* ei) {
    int e = (blockIdx.x * 256 + threadIdx.x) * 2;
    if (e >= NE) return;
    int s0, s1, d0, d1;
    if (g_is64) {
        const long long* p = (const long long*)ei;
        longlong2 sp = __ldg((const longlong2*)p + (e >> 1));
        longlong2 dp = __ldg((const longlong2*)(p + NE) + (e >> 1));
        s0 = (int)sp.x; s1 = (int)sp.y; d0 = (int)dp.x; d1 = (int)dp.y;
    } else {
        const int* p = (const int*)ei;
        int2 sp = __ldg((const int2*)p + (e >> 1));
        int2 dp = __ldg((const int2*)(p + NE) + (e >> 1));
        s0 = sp.x; s1 = sp.y; d0 = dp.x; d1 = dp.y;
    }
    g_csr[atomicAdd(&g_cur[d0], 1)] = s0;
    g_csr[atomicAdd(&g_cur[d1], 1)] = s1;
}

// gather h[w] = x[w] + sum_j x[csr[j]]  -> bf16 hi/lo split, one warp per node
__global__ __launch_bounds__(256)
void gather_bf16_kernel(const float* __restrict__ x,
                        uint32_t* __restrict__ hi, uint32_t* __restrict__ lo) {
    int w = (blockIdx.x * 256 + threadIdx.x) >> 5;
    int lane = threadIdx.x & 31;
    if (w >= NN) return;
    const float4* xb = (const float4*)x;
    float4 acc = __ldg(xb + (size_t)w * 32 + lane);
    int i = g_off[w];
    int end = i + g_deg[w];
    for (; i + 4 <= end; i += 4) {
        int s0 = __ldg(g_csr + i),     s1 = __ldg(g_csr + i + 1);
        int s2 = __ldg(g_csr + i + 2), s3 = __ldg(g_csr + i + 3);
        float4 v0 = __ldg(xb + (size_t)s0 * 32 + lane);
        float4 v1 = __ldg(xb + (size_t)s1 * 32 + lane);
        float4 v2 = __ldg(xb + (size_t)s2 * 32 + lane);
        float4 v3 = __ldg(xb + (size_t)s3 * 32 + lane);
        acc.x += (v0.x + v1.x) + (v2.x + v3.x);
        acc.y += (v0.y + v1.y) + (v2.y + v3.y);
        acc.z += (v0.z + v1.z) + (v2.z + v3.z);
        acc.w += (v0.w + v1.w) + (v2.w + v3.w);
    }
    for (; i < end; ++i) {
        int s = __ldg(g_csr + i);
        float4 v = __ldg(xb + (size_t)s * 32 + lane);
        acc.x += v.x; acc.y += v.y; acc.z += v.z; acc.w += v.w;
    }
    uint32_t h0, l0, h1, l1;
    split2(acc.x, acc.y, h0, l0);
    split2(acc.z, acc.w, h1, l1);
    ((uint2*)hi)[(size_t)w * 32 + lane] = make_uint2(h0, h1);
    ((uint2*)lo)[(size_t)w * 32 + lane] = make_uint2(l0, l1);
}

// conv: fp32 -> bf16 hi/lo with BN+ReLU; scale/shift computed per-BLOCK in smem
__global__ __launch_bounds__(256)
void conv_split_bn_kernel(const float* __restrict__ C,
                          uint32_t* __restrict__ hi, uint32_t* __restrict__ lo,
                          const float* __restrict__ stats,
                          const float* __restrict__ gamma,
                          const float* __restrict__ beta) {
    __shared__ float sc_s[128], sh_s[128];
    int tid = threadIdx.x;
    if (tid < 128) {
        float mu  = stats[tid] * (1.0f / NN);
        float var = stats[128 + tid] * (1.0f / NN) - mu * mu;
        float sc  = __ldg(gamma + tid) * rsqrtf(var + 1e-5f);
        sc_s[tid] = sc;
        sh_s[tid] = __ldg(beta + tid) - mu * sc;
    }
    __syncthreads();
    int i = blockIdx.x * 256 + tid;
    if (i >= NN * 32) return;
    float4 v = __ldg((const float4*)C + i);
    int k = (i & 31) * 4;
    float4 sc = *(const float4*)(sc_s + k);
    float4 sh = *(const float4*)(sh_s + k);
    v.x = fmaxf(fmaf(v.x, sc.x, sh.x), 0.f);
    v.y = fmaxf(fmaf(v.y, sc.y, sh.y), 0.f);
    v.z = fmaxf(fmaf(v.z, sc.z, sh.z), 0.f);
    v.w = fmaxf(fmaf(v.w, sc.w, sh.w), 0.f);
    uint32_t h0, l0, h1, l1;
    split2(v.x, v.y, h0, l0);
    split2(v.z, v.w, h1, l1);
    ((uint2*)hi)[i] = make_uint2(h0, h1);
    ((uint2*)lo)[i] = make_uint2(l0, l1);
}

// ---------------- HMMA GEMM: Out = split(A) @ Wt^T + bias ----------------
// STATS: fused column sum/sumsq of Out into stats[0:256) (shfl-reduced epilogue).
// EMIT:  0 = store fp32 Out; 1 = store bf16 hi/lo split to Ohi/Olo.
//        EMIT destinations must NOT alias Ahi/Alo (host guarantees).
template <int NOUT, bool RELU, bool STATS, int EMIT>
__global__ __launch_bounds__(256, 2)
void mma_gemm(const uint32_t* __restrict__ Ahi, const uint32_t* __restrict__ Alo,
              const uint32_t* __restrict__ Wh, const uint32_t* __restrict__ Wl,
              const float* __restrict__ bias, float* __restrict__ Out,
              uint32_t* __restrict__ Ohi, uint32_t* __restrict__ Olo,
              float* __restrict__ stats) {
    constexpr int WM = (NOUT == 128) ? 4 : 8;   // warps along m
    constexpr int MF = 128 / (WM * 16);         // m16 frags per warp
    constexpr int RS = 68;                      // smem row stride (u32): lane bank = 4g+tig, conflict-free
    extern __shared__ uint32_t ws[];
    uint32_t* wh_s = ws;
    uint32_t* wl_s = ws + NOUT * RS;
    __shared__ float ssum[128], ssq[128];

    int tid = threadIdx.x;
    for (int i = tid; i < NOUT * 64; i += 256) {
        int n = i >> 6, kw = i & 63;
        wh_s[n * RS + kw] = __ldg(Wh + i);
        wl_s[n * RS + kw] = __ldg(Wl + i);
    }
    if (STATS && tid < 128) { ssum[tid] = 0.f; ssq[tid] = 0.f; }
    __syncthreads();

    int wid = tid >> 5, lane = tid & 31;
    int g = lane >> 2, tig = lane & 3;
    int mwid = wid % WM, nwid = wid / WM;
    int n0 = nwid * 64;
    int mbase = blockIdx.x * MT + mwid * (MF * 16);

    float acc[MF][8][4];
#pragma unroll
    for (int mf = 0; mf < MF; ++mf)
#pragma unroll
        for (int nf = 0; nf < 8; ++nf)
#pragma unroll
            for (int c = 0; c < 4; ++c) acc[mf][nf][c] = 0.f;

    for (int ks = 0; ks < 8; ++ks) {
        uint32_t ah[MF][4], al[MF][4];
#pragma unroll
        for (int mf = 0; mf < MF; ++mf) {
            int r0 = mbase + mf * 16 + g;
            int r1 = r0 + 8;
            int o = ks * 8 + tig;
            bool v0 = r0 < NN, v1 = r1 < NN;
            size_t p0 = (size_t)r0 * 64 + o, p1 = (size_t)r1 * 64 + o;
            ah[mf][0] = v0 ? __ldg(Ahi + p0) : 0u;
            ah[mf][1] = v1 ? __ldg(Ahi + p1) : 0u;
            ah[mf][2] = v0 ? __ldg(Ahi + p0 + 4) : 0u;
            ah[mf][3] = v1 ? __ldg(Ahi + p1 + 4) : 0u;
            al[mf][0] = v0 ? __ldg(Alo + p0) : 0u;
            al[mf][1] = v1 ? __ldg(Alo + p1) : 0u;
            al[mf][2] = v0 ? __ldg(Alo + p0 + 4) : 0u;
            al[mf][3] = v1 ? __ldg(Alo + p1 + 4) : 0u;
        }
#pragma unroll
        for (int nf = 0; nf < 8; ++nf) {
            int bo = (n0 + nf * 8 + g) * RS + ks * 8 + tig;
            uint32_t bh0 = wh_s[bo], bh1 = wh_s[bo + 4];
            uint32_t bl0 = wl_s[bo], bl1 = wl_s[bo + 4];
#pragma unroll
            for (int mf = 0; mf < MF; ++mf) {
                MMA_BF16(acc[mf][nf], ah[mf], bh0, bh1);
                MMA_BF16(acc[mf][nf], al[mf], bh0, bh1);
                MMA_BF16(acc[mf][nf], ah[mf], bl0, bl1);
            }
        }
    }

#pragma unroll
    for (int nf = 0; nf < 8; ++nf) {
        int col = n0 + nf * 8 + tig * 2;
        float2 b = *(const float2*)(bias + col);
        float s0 = 0.f, s1 = 0.f, q0 = 0.f, q1 = 0.f;
#pragma unroll
        for (int mf = 0; mf < MF; ++mf) {
            int r0 = mbase + mf * 16 + g;
            int r1 = r0 + 8;
            float c0 = acc[mf][nf][0] + b.x, c1 = acc[mf][nf][1] + b.y;
            float c2 = acc[mf][nf][2] + b.x, c3 = acc[mf][nf][3] + b.y;
            if (RELU) {
                c0 = fmaxf(c0, 0.f); c1 = fmaxf(c1, 0.f);
                c2 = fmaxf(c2, 0.f); c3 = fmaxf(c3, 0.f);
            }
            if (r0 < NN) {
                if (EMIT) {
                    uint32_t hh, ll;
                    split2(c0, c1, hh, ll);
                    Ohi[(size_t)r0 * 64 + col / 2] = hh;
                    Olo[(size_t)r0 * 64 + col / 2] = ll;
                } else {
                    *(float2*)(Out + (size_t)r0 * NOUT + col) = make_float2(c0, c1);
                }
                if (STATS) { s0 += c0; s1 += c1; q0 += c0 * c0; q1 += c1 * c1; }
            }
            if (r1 < NN) {
                if (EMIT) {
                    uint32_t hh, ll;
                    split2(c2, c3, hh, ll);
                    Ohi[(size_t)r1 * 64 + col / 2] = hh;
                    Olo[(size_t)r1 * 64 + col / 2] = ll;
                } else {
                    *(float2*)(Out + (size_t)r1 * NOUT + col) = make_float2(c2, c3);
                }
                if (STATS) { s0 += c2; s1 += c3; q0 += c2 * c2; q1 += c3 * c3; }
            }
        }
        if (STATS) {
#pragma unroll
            for (int o = 4; o < 32; o <<= 1) {
                s0 += __shfl_xor_sync(0xFFFFFFFFu, s0, o);
                s1 += __shfl_xor_sync(0xFFFFFFFFu, s1, o);
                q0 += __shfl_xor_sync(0xFFFFFFFFu, q0, o);
                q1 += __shfl_xor_sync(0xFFFFFFFFu, q1, o);
            }
            if (lane < 4) {
                atomicAdd(&ssum[col], s0);
                atomicAdd(&ssum[col + 1], s1);
                atomicAdd(&ssq[col], q0);
                atomicAdd(&ssq[col + 1], q1);
            }
        }
    }
    if (STATS) {
        __syncthreads();
        if (tid < 128) {
            atomicAdd(&stats[tid], ssum[tid]);
            atomicAdd(&stats[128 + tid], ssq[tid]);
        }
    }
}

// ---------------- host ----------------
extern "C" void kernel_launch(void* const* d_in, const int* in_sizes, int n_in,
                              void* d_out, int out_size) {
    const float* x    = (const float*)d_in[0];
    const void*  ei   = d_in[1];
    const float* W1   = (const float*)d_in[2];
    const float* b1   = (const float*)d_in[3];
    const float* g1   = (const float*)d_in[4];
    const float* be1  = (const float*)d_in[5];
    const float* W2   = (const float*)d_in[6];
    const float* b2   = (const float*)d_in[7];
    const float* fW1  = (const float*)d_in[8];
    const float* fb1  = (const float*)d_in[9];
    const float* fg1  = (const float*)d_in[10];
    const float* fbe1 = (const float*)d_in[11];
    const float* fW2  = (const float*)d_in[12];
    const float* fb2  = (const float*)d_in[13];
    float* out = (float*)d_out;

    float *A, *C, *st;
    uint32_t *hi, *lo, *wh, *wl;
    cudaGetSymbolAddress((void**)&A, g_bufA);
    cudaGetSymbolAddress((void**)&C, g_bufC);
    cudaGetSymbolAddress((void**)&st, g_stats2);
    cudaGetSymbolAddress((void**)&hi, g_hi);
    cudaGetSymbolAddress((void**)&lo, g_lo);
    cudaGetSymbolAddress((void**)&wh, g_wh);
    cudaGetSymbolAddress((void**)&wl, g_wl);
    uint32_t* Chi = (uint32_t*)C;                    // layer-3 EMIT hi (C is dead then)
    uint32_t* Clo = (uint32_t*)C + (size_t)NN * 64;  // layer-3 EMIT lo

    const int SMA = 128 * 68 * 4 * 2;   // 69632 B
    const int SMB = 64 * 68 * 4 * 2;    // 34816 B
    cudaFuncSetAttribute(mma_gemm<128, false, true, 0>,
                         cudaFuncAttributeMaxDynamicSharedMemorySize, SMA);
    cudaFuncSetAttribute(mma_gemm<128, true, false, 0>,
                         cudaFuncAttributeMaxDynamicSharedMemorySize, SMA);
    cudaFuncSetAttribute(mma_gemm<128, true, false, 1>,
                         cudaFuncAttributeMaxDynamicSharedMemorySize, SMA);
    cudaFuncSetAttribute(mma_gemm<64, false, false, 0>,
                         cudaFuncAttributeMaxDynamicSharedMemorySize, SMB);

    init_kernel<<<SCANB + 1, 256>>>(ei);
    prep_w<<<dim3(64, 8), 256>>>(W1, W2, fW1, fW2);
    hist_kernel<<<NE / 512, 256>>>(ei);
    scan1_kernel<<<SCANB, 256>>>();
    scan2_kernel<<<1, 512>>>();
    scan3_kernel<<<SCANB, 256>>>();
    fill_kernel<<<NE / 512, 256>>>(ei);

    const int gblocks = (NN * 32 + 255) / 256;   // 12500
    const int cblocks = (NN * 32 + 255) / 256;

    const float* cur = x;
    for (int l = 0; l < 3; ++l) {
        float* slot = st + l * 256;
        gather_bf16_kernel<<<gblocks, 256>>>(cur, hi, lo);
        mma_gemm<128, false, true, 0><<<NBLK, 256, SMA>>>(
            hi, lo, wh + (size_t)l * D * 64, wl + (size_t)l * D * 64, b1 + l * D, C,
            nullptr, nullptr, slot);
        conv_split_bn_kernel<<<cblocks, 256>>>(C, hi, lo, slot, g1 + l * D, be1 + l * D);
        if (l < 2) {
            mma_gemm<128, true, false, 0><<<NBLK, 256, SMA>>>(
                hi, lo, wh + (size_t)(3 + l) * D * 64, wl + (size_t)(3 + l) * D * 64,
                b2 + l * D, A, nullptr, nullptr, nullptr);
            cur = A;
        } else {
            // layer-3 GEMM2: emit bf16 hi/lo into g_bufC's storage (no aliasing)
            mma_gemm<128, true, false, 1><<<NBLK, 256, SMA>>>(
                hi, lo, wh + (size_t)(3 + l) * D * 64, wl + (size_t)(3 + l) * D * 64,
                b2 + l * D, nullptr, Chi, Clo, nullptr);
        }
    }
    // final MLP: read Chi/Clo, write fp32 to A (dead), conv -> g_hi/g_lo, last GEMM -> out
    mma_gemm<128, false, true, 0><<<NBLK, 256, SMA>>>(
        Chi, Clo, wh + (size_t)6 * D * 64, wl + (size_t)6 * D * 64, fb1, A,
        nullptr, nullptr, st + 3 * 256);
    conv_split_bn_kernel<<<cblocks, 256>>>(A, hi, lo, st + 3 * 256, fg1, fbe1);
    mma_gemm<64, false, false, 0><<<NBLK, 256, SMB>>>(
        hi, lo, wh + (size_t)7 * D * 64, wl + (size_t)7 * D * 64, fb2, out,
        nullptr, nullptr, nullptr);
}

// round 14
// speedup vs baseline: 1.0664x; 1.0220x over previous
#include <cuda_runtime.h>
#include <cuda_bf16.h>
#include <cstdint>

#define NN   100000
#define NE   1600000
#define D    128
#define DOUT 64
#define MT   128
#define NBLK ((NN + MT - 1) / MT)     // 782
#define SCANB ((NN + 255) / 256)      // 391

// ---------------- scratch ----------------
__device__ __align__(16) float g_bufA[NN * D];
__device__ __align__(16) float g_bufC[NN * D];
__device__ __align__(16) uint32_t g_hi[NN * (D / 2)];
__device__ __align__(16) uint32_t g_lo[NN * (D / 2)];
__device__ __align__(16) float g_stats2[4 * 256];  // per-stats-GEMM: [sum(128), sumsq(128)]
__device__ int g_is64;
__device__ int g_deg[NN];
__device__ int g_off[NN];
__device__ int g_cur[NN];
__device__ int g_csr[NE];
__device__ int g_bsum[512];
__device__ __align__(16) __nv_bfloat16 g_wh[8 * D * D];
__device__ __align__(16) __nv_bfloat16 g_wl[8 * D * D];

__device__ __forceinline__ uint32_t pack2(__nv_bfloat16 a, __nv_bfloat16 b) {
    return (uint32_t)__bfloat16_as_ushort(a) | ((uint32_t)__bfloat16_as_ushort(b) << 16);
}
__device__ __forceinline__ void split2(float x, float y, uint32_t& h, uint32_t& l) {
    __nv_bfloat16 hx = __float2bfloat16(x), hy = __float2bfloat16(y);
    h = pack2(hx, hy);
    l = pack2(__float2bfloat16(x - __bfloat162float(hx)),
              __float2bfloat16(y - __bfloat162float(hy)));
}

#define MMA_BF16(c, a, b0_, b1_) \
    asm volatile("mma.sync.aligned.m16n8k16.row.col.f32.bf16.bf16.f32 " \
        "{%0,%1,%2,%3}, {%4,%5,%6,%7}, {%8,%9}, {%0,%1,%2,%3};" \
        : "+f"((c)[0]), "+f"((c)[1]), "+f"((c)[2]), "+f"((c)[3]) \
        : "r"((a)[0]), "r"((a)[1]), "r"((a)[2]), "r"((a)[3]), "r"(b0_), "r"(b1_))

// ---------------- init: zero deg + detect dtype + zero stats slots ----------------
__global__ void init_kernel(const void* ei) {
    if (blockIdx.x < SCANB) {
        int i = blockIdx.x * 256 + threadIdx.x;
        if (i < NN) g_deg[i] = 0;
    } else {
        const long long* p = (const long long*)ei;
        long long v = p[threadIdx.x];
        int ok = (v >= 0 && v < NN);
        ok = __syncthreads_and(ok);
        if (threadIdx.x == 0) g_is64 = ok;
        ((float4*)g_stats2)[threadIdx.x] = make_float4(0.f, 0.f, 0.f, 0.f);
    }
}

// transpose + bf16-split all 8 weight matrices: g_wh/g_wl[m][n][k]
__global__ void prep_w(const float* __restrict__ W1, const float* __restrict__ W2,
                       const float* __restrict__ fW1, const float* __restrict__ fW2) {
    int m = blockIdx.y;
    const float* src;
    int ncols;
    if (m < 3)       { src = W1 + m * D * D;       ncols = D; }
    else if (m < 6)  { src = W2 + (m - 3) * D * D; ncols = D; }
    else if (m == 6) { src = fW1;                  ncols = D; }
    else             { src = fW2;                  ncols = DOUT; }
    int idx = blockIdx.x * 256 + threadIdx.x;
    if (idx >= ncols * D) return;
    int n = idx / D, k = idx % D;
    float v = __ldg(src + k * ncols + n);
    __nv_bfloat16 h = __float2bfloat16(v);
    g_wh[m * D * D + idx] = h;
    g_wl[m * D * D + idx] = __float2bfloat16(v - __bfloat162float(h));
}

// histogram of dst, 2 edges per thread (128-bit index loads)
__global__ void hist_kernel(const void* ei) {
    int e = (blockIdx.x * 256 + threadIdx.x) * 2;
    if (e >= NE) return;
    int d0, d1;
    if (g_is64) {
        longlong2 p = __ldg((const longlong2*)((const long long*)ei + NE) + (e >> 1));
        d0 = (int)p.x; d1 = (int)p.y;
    } else {
        int2 p = __ldg((const int2*)((const int*)ei + NE) + (e >> 1));
        d0 = p.x; d1 = p.y;
    }
    atomicAdd(&g_deg[d0], 1);
    atomicAdd(&g_deg[d1], 1);
}
__global__ void scan1_kernel() {
    __shared__ int s[256];
    int i = blockIdx.x * 256 + threadIdx.x;
    int v = (i < NN) ? g_deg[i] : 0;
    s[threadIdx.x] = v;
    __syncthreads();
    for (int o = 1; o < 256; o <<= 1) {
        int t = (threadIdx.x >= o) ? s[threadIdx.x - o] : 0;
        __syncthreads();
        s[threadIdx.x] += t;
        __syncthreads();
    }
    if (i < NN) g_off[i] = s[threadIdx.x];
    if (threadIdx.x == 255) g_bsum[blockIdx.x] = s[255];
}
__global__ void scan2_kernel() {
    __shared__ int s[512];
    int v = (threadIdx.x < SCANB) ? g_bsum[threadIdx.x] : 0;
    s[threadIdx.x] = v;
    __syncthreads();
    for (int o = 1; o < 512; o <<= 1) {
        int t = (threadIdx.x >= o) ? s[threadIdx.x - o] : 0;
        __syncthreads();
        s[threadIdx.x] += t;
        __syncthreads();
    }
    g_bsum[threadIdx.x] = s[threadIdx.x] - v;
}
__global__ void scan3_kernel() {
    int i = blockIdx.x * 256 + threadIdx.x;
    if (i >= NN) return;
    int e = g_off[i] - g_deg[i] + g_bsum[blockIdx.x];
    g_off[i] = e;
    g_cur[i] = e;
}
// CSR fill, 2 edges per thread
__global__ void fill_kernel(const void* ei) {
    int e = (blockIdx.x * 256 + threadIdx.x) * 2;
    if (e >= NE) return;
    int s0, s1, d0, d1;
    if (g_is64) {
        const long long* p = (const long long*)ei;
        longlong2 sp = __ldg((const longlong2*)p + (e >> 1));
        longlong2 dp = __ldg((const longlong2*)(p + NE) + (e >> 1));
        s0 = (int)sp.x; s1 = (int)sp.y; d0 = (int)dp.x; d1 = (int)dp.y;
    } else {
        const int* p = (const int*)ei;
        int2 sp = __ldg((const int2*)p + (e >> 1));
        int2 dp = __ldg((const int2*)(p + NE) + (e >> 1));
        s0 = sp.x; s1 = sp.y; d0 = dp.x; d1 = dp.y;
    }
    g_csr[atomicAdd(&g_cur[d0], 1)] = s0;
    g_csr[atomicAdd(&g_cur[d1], 1)] = s1;
}

// gather h[w] = x[w] + sum_j x[csr[j]]  -> bf16 hi/lo split, one warp per node
__global__ __launch_bounds__(256)
void gather_bf16_kernel(const float* __restrict__ x,
                        uint32_t* __restrict__ hi, uint32_t* __restrict__ lo) {
    int w = (blockIdx.x * 256 + threadIdx.x) >> 5;
    int lane = threadIdx.x & 31;
    if (w >= NN) return;
    const float4* xb = (const float4*)x;
    float4 acc = __ldg(xb + (size_t)w * 32 + lane);
    int i = g_off[w];
    int end = i + g_deg[w];
    for (; i + 4 <= end; i += 4) {
        int s0 = __ldg(g_csr + i),     s1 = __ldg(g_csr + i + 1);
        int s2 = __ldg(g_csr + i + 2), s3 = __ldg(g_csr + i + 3);
        float4 v0 = __ldg(xb + (size_t)s0 * 32 + lane);
        float4 v1 = __ldg(xb + (size_t)s1 * 32 + lane);
        float4 v2 = __ldg(xb + (size_t)s2 * 32 + lane);
        float4 v3 = __ldg(xb + (size_t)s3 * 32 + lane);
        acc.x += (v0.x + v1.x) + (v2.x + v3.x);
        acc.y += (v0.y + v1.y) + (v2.y + v3.y);
        acc.z += (v0.z + v1.z) + (v2.z + v3.z);
        acc.w += (v0.w + v1.w) + (v2.w + v3.w);
    }
    for (; i < end; ++i) {
        int s = __ldg(g_csr + i);
        float4 v = __ldg(xb + (size_t)s * 32 + lane);
        acc.x += v.x; acc.y += v.y; acc.z += v.z; acc.w += v.w;
    }
    uint32_t h0, l0, h1, l1;
    split2(acc.x, acc.y, h0, l0);
    split2(acc.z, acc.w, h1, l1);
    ((uint2*)hi)[(size_t)w * 32 + lane] = make_uint2(h0, h1);
    ((uint2*)lo)[(size_t)w * 32 + lane] = make_uint2(l0, l1);
}

// conv: fp32 -> bf16 hi/lo with BN+ReLU; scale/shift computed per-BLOCK in smem
__global__ __launch_bounds__(256)
void conv_split_bn_kernel(const float* __restrict__ C,
                          uint32_t* __restrict__ hi, uint32_t* __restrict__ lo,
                          const float* __restrict__ stats,
                          const float* __restrict__ gamma,
                          const float* __restrict__ beta) {
    __shared__ float sc_s[128], sh_s[128];
    int tid = threadIdx.x;
    if (tid < 128) {
        float mu  = stats[tid] * (1.0f / NN);
        float var = stats[128 + tid] * (1.0f / NN) - mu * mu;
        float sc  = __ldg(gamma + tid) * rsqrtf(var + 1e-5f);
        sc_s[tid] = sc;
        sh_s[tid] = __ldg(beta + tid) - mu * sc;
    }
    __syncthreads();
    int i = blockIdx.x * 256 + tid;
    if (i >= NN * 32) return;
    float4 v = __ldg((const float4*)C + i);
    int k = (i & 31) * 4;
    float4 sc = *(const float4*)(sc_s + k);
    float4 sh = *(const float4*)(sh_s + k);
    v.x = fmaxf(fmaf(v.x, sc.x, sh.x), 0.f);
    v.y = fmaxf(fmaf(v.y, sc.y, sh.y), 0.f);
    v.z = fmaxf(fmaf(v.z, sc.z, sh.z), 0.f);
    v.w = fmaxf(fmaf(v.w, sc.w, sh.w), 0.f);
    uint32_t h0, l0, h1, l1;
    split2(v.x, v.y, h0, l0);
    split2(v.z, v.w, h1, l1);
    ((uint2*)hi)[i] = make_uint2(h0, h1);
    ((uint2*)lo)[i] = make_uint2(l0, l1);
}

// ---------------- HMMA GEMM: Out = split(A) @ Wt^T + bias ----------------
// STATS: fused column sum/sumsq of Out into stats[0:256) (shfl-reduced epilogue).
// EMIT:  0 = store fp32 Out; 1 = store bf16 hi/lo split to Ohi/Olo (no aliasing, host-guaranteed).
template <int NOUT, bool RELU, bool STATS, int EMIT>
__global__ __launch_bounds__(256, 2)
void mma_gemm(const uint32_t* __restrict__ Ahi, const uint32_t* __restrict__ Alo,
              const uint32_t* __restrict__ Wh, const uint32_t* __restrict__ Wl,
              const float* __restrict__ bias, float* __restrict__ Out,
              uint32_t* __restrict__ Ohi, uint32_t* __restrict__ Olo,
              float* __restrict__ stats) {
    constexpr int WM = (NOUT == 128) ? 4 : 8;   // warps along m
    constexpr int MF = 128 / (WM * 16);         // m16 frags per warp
    constexpr int RS = 68;                      // smem row stride (u32): lane bank = 4g+tig, conflict-free; RS%4==0 for uint4 staging
    extern __shared__ uint32_t ws[];
    uint32_t* wh_s = ws;
    uint32_t* wl_s = ws + NOUT * RS;
    __shared__ float ssum[128], ssq[128];

    int tid = threadIdx.x;
    // 128-bit W staging: i-th uint4 covers u32 idx 4i..4i+3, row n = i>>4, kw4 = i&15 (kw=4*kw4<=60 < RS-3)
    for (int i = tid; i < NOUT * 16; i += 256) {
        int n = i >> 4, kw4 = i & 15;
        uint4 vh = __ldg((const uint4*)Wh + i);
        uint4 vl = __ldg((const uint4*)Wl + i);
        *(uint4*)(wh_s + n * RS + kw4 * 4) = vh;
        *(uint4*)(wl_s + n * RS + kw4 * 4) = vl;
    }
    if (STATS && tid < 128) { ssum[tid] = 0.f; ssq[tid] = 0.f; }
    __syncthreads();

    int wid = tid >> 5, lane = tid & 31;
    int g = lane >> 2, tig = lane & 3;
    int mwid = wid % WM, nwid = wid / WM;
    int n0 = nwid * 64;
    int mbase = blockIdx.x * MT + mwid * (MF * 16);

    float acc[MF][8][4];
#pragma unroll
    for (int mf = 0; mf < MF; ++mf)
#pragma unroll
        for (int nf = 0; nf < 8; ++nf)
#pragma unroll
            for (int c = 0; c < 4; ++c) acc[mf][nf][c] = 0.f;

    for (int ks = 0; ks < 8; ++ks) {
        uint32_t ah[MF][4], al[MF][4];
#pragma unroll
        for (int mf = 0; mf < MF; ++mf) {
            int r0 = mbase + mf * 16 + g;
            int r1 = r0 + 8;
            int o = ks * 8 + tig;
            bool v0 = r0 < NN, v1 = r1 < NN;
            size_t p0 = (size_t)r0 * 64 + o, p1 = (size_t)r1 * 64 + o;
            ah[mf][0] = v0 ? __ldg(Ahi + p0) : 0u;
            ah[mf][1] = v1 ? __ldg(Ahi + p1) : 0u;
            ah[mf][2] = v0 ? __ldg(Ahi + p0 + 4) : 0u;
            ah[mf][3] = v1 ? __ldg(Ahi + p1 + 4) : 0u;
            al[mf][0] = v0 ? __ldg(Alo + p0) : 0u;
            al[mf][1] = v1 ? __ldg(Alo + p1) : 0u;
            al[mf][2] = v0 ? __ldg(Alo + p0 + 4) : 0u;
            al[mf][3] = v1 ? __ldg(Alo + p1 + 4) : 0u;
        }
#pragma unroll
        for (int nf = 0; nf < 8; ++nf) {
            int bo = (n0 + nf * 8 + g) * RS + ks * 8 + tig;
            uint32_t bh0 = wh_s[bo], bh1 = wh_s[bo + 4];
            uint32_t bl0 = wl_s[bo], bl1 = wl_s[bo + 4];
#pragma unroll
            for (int mf = 0; mf < MF; ++mf) {
                MMA_BF16(acc[mf][nf], ah[mf], bh0, bh1);
                MMA_BF16(acc[mf][nf], al[mf], bh0, bh1);
                MMA_BF16(acc[mf][nf], ah[mf], bl0, bl1);
            }
        }
    }

#pragma unroll
    for (int nf = 0; nf < 8; ++nf) {
        int col = n0 + nf * 8 + tig * 2;
        float2 b = *(const float2*)(bias + col);
        float s0 = 0.f, s1 = 0.f, q0 = 0.f, q1 = 0.f;
#pragma unroll
        for (int mf = 0; mf < MF; ++mf) {
            int r0 = mbase + mf * 16 + g;
            int r1 = r0 + 8;
            float c0 = acc[mf][nf][0] + b.x, c1 = acc[mf][nf][1] + b.y;
            float c2 = acc[mf][nf][2] + b.x, c3 = acc[mf][nf][3] + b.y;
            if (RELU) {
                c0 = fmaxf(c0, 0.f); c1 = fmaxf(c1, 0.f);
                c2 = fmaxf(c2, 0.f); c3 = fmaxf(c3, 0.f);
            }
            if (r0 < NN) {
                if (EMIT) {
                    uint32_t hh, ll;
                    split2(c0, c1, hh, ll);
                    Ohi[(size_t)r0 * 64 + col / 2] = hh;
                    Olo[(size_t)r0 * 64 + col / 2] = ll;
                } else {
                    *(float2*)(Out + (size_t)r0 * NOUT + col) = make_float2(c0, c1);
                }
                if (STATS) { s0 += c0; s1 += c1; q0 += c0 * c0; q1 += c1 * c1; }
            }
            if (r1 < NN) {
                if (EMIT) {
                    uint32_t hh, ll;
                    split2(c2, c3, hh, ll);
                    Ohi[(size_t)r1 * 64 + col / 2] = hh;
                    Olo[(size_t)r1 * 64 + col / 2] = ll;
                } else {
                    *(float2*)(Out + (size_t)r1 * NOUT + col) = make_float2(c2, c3);
                }
                if (STATS) { s0 += c2; s1 += c3; q0 += c2 * c2; q1 += c3 * c3; }
            }
        }
        if (STATS) {
#pragma unroll
            for (int o = 4; o < 32; o <<= 1) {
                s0 += __shfl_xor_sync(0xFFFFFFFFu, s0, o);
                s1 += __shfl_xor_sync(0xFFFFFFFFu, s1, o);
                q0 += __shfl_xor_sync(0xFFFFFFFFu, q0, o);
                q1 += __shfl_xor_sync(0xFFFFFFFFu, q1, o);
            }
            if (lane < 4) {
                atomicAdd(&ssum[col], s0);
                atomicAdd(&ssum[col + 1], s1);
                atomicAdd(&ssq[col], q0);
                atomicAdd(&ssq[col + 1], q1);
            }
        }
    }
    if (STATS) {
        __syncthreads();
        if (tid < 128) {
            atomicAdd(&stats[tid], ssum[tid]);
            atomicAdd(&stats[128 + tid], ssq[tid]);
        }
    }
}

// ---------------- host ----------------
extern "C" void kernel_launch(void* const* d_in, const int* in_sizes, int n_in,
                              void* d_out, int out_size) {
    const float* x    = (const float*)d_in[0];
    const void*  ei   = d_in[1];
    const float* W1   = (const float*)d_in[2];
    const float* b1   = (const float*)d_in[3];
    const float* g1   = (const float*)d_in[4];
    const float* be1  = (const float*)d_in[5];
    const float* W2   = (const float*)d_in[6];
    const float* b2   = (const float*)d_in[7];
    const float* fW1  = (const float*)d_in[8];
    const float* fb1  = (const float*)d_in[9];
    const float* fg1  = (const float*)d_in[10];
    const float* fbe1 = (const float*)d_in[11];
    const float* fW2  = (const float*)d_in[12];
    const float* fb2  = (const float*)d_in[13];
    float* out = (float*)d_out;

    float *A, *C, *st;
    uint32_t *hi, *lo, *wh, *wl;
    cudaGetSymbolAddress((void**)&A, g_bufA);
    cudaGetSymbolAddress((void**)&C, g_bufC);
    cudaGetSymbolAddress((void**)&st, g_stats2);
    cudaGetSymbolAddress((void**)&hi, g_hi);
    cudaGetSymbolAddress((void**)&lo, g_lo);
    cudaGetSymbolAddress((void**)&wh, g_wh);
    cudaGetSymbolAddress((void**)&wl, g_wl);
    uint32_t* Chi = (uint32_t*)C;                    // layer-3 EMIT hi (C is dead then)
    uint32_t* Clo = (uint32_t*)C + (size_t)NN * 64;  // layer-3 EMIT lo

    const int SMA = 128 * 68 * 4 * 2;   // 69632 B
    const int SMB = 64 * 68 * 4 * 2;    // 34816 B
    cudaFuncSetAttribute(mma_gemm<128, false, true, 0>,
                         cudaFuncAttributeMaxDynamicSharedMemorySize, SMA);
    cudaFuncSetAttribute(mma_gemm<128, true, false, 0>,
                         cudaFuncAttributeMaxDynamicSharedMemorySize, SMA);
    cudaFuncSetAttribute(mma_gemm<128, true, false, 1>,
                         cudaFuncAttributeMaxDynamicSharedMemorySize, SMA);
    cudaFuncSetAttribute(mma_gemm<64, false, false, 0>,
                         cudaFuncAttributeMaxDynamicSharedMemorySize, SMB);

    init_kernel<<<SCANB + 1, 256>>>(ei);
    prep_w<<<dim3(64, 8), 256>>>(W1, W2, fW1, fW2);
    hist_kernel<<<NE / 512, 256>>>(ei);
    scan1_kernel<<<SCANB, 256>>>();
    scan2_kernel<<<1, 512>>>();
    scan3_kernel<<<SCANB, 256>>>();
    fill_kernel<<<NE / 512, 256>>>(ei);

    const int gblocks = (NN * 32 + 255) / 256;   // 12500
    const int cblocks = (NN * 32 + 255) / 256;

    const float* cur = x;
    for (int l = 0; l < 3; ++l) {
        float* slot = st + l * 256;
        gather_bf16_kernel<<<gblocks, 256>>>(cur, hi, lo);
        mma_gemm<128, false, true, 0><<<NBLK, 256, SMA>>>(
            hi, lo, wh + (size_t)l * D * 64, wl + (size_t)l * D * 64, b1 + l * D, C,
            nullptr, nullptr, slot);
        conv_split_bn_kernel<<<cblocks, 256>>>(C, hi, lo, slot, g1 + l * D, be1 + l * D);
        if (l < 2) {
            mma_gemm<128, true, false, 0><<<NBLK, 256, SMA>>>(
                hi, lo, wh + (size_t)(3 + l) * D * 64, wl + (size_t)(3 + l) * D * 64,
                b2 + l * D, A, nullptr, nullptr, nullptr);
            cur = A;
        } else {
            // layer-3 GEMM2: emit bf16 hi/lo into g_bufC's storage (no aliasing)
            mma_gemm<128, true, false, 1><<<NBLK, 256, SMA>>>(
                hi, lo, wh + (size_t)(3 + l) * D * 64, wl + (size_t)(3 + l) * D * 64,
                b2 + l * D, nullptr, Chi, Clo, nullptr);
        }
    }
    // final MLP: read Chi/Clo, write fp32 to A (dead), conv -> g_hi/g_lo, last GEMM -> out
    mma_gemm<128, false, true, 0><<<NBLK, 256, SMA>>>(
        Chi, Clo, wh + (size_t)6 * D * 64, wl + (size_t)6 * D * 64, fb1, A,
        nullptr, nullptr, st + 3 * 256);
    conv_split_bn_kernel<<<cblocks, 256>>>(A, hi, lo, st + 3 * 256, fg1, fbe1);
    mma_gemm<64, false, false, 0><<<NBLK, 256, SMB>>>(
        hi, lo, wh + (size_t)7 * D * 64, wl + (size_t)7 * D * 64, fb2, out,
        nullptr, nullptr, nullptr);
}

// round 15
// speedup vs baseline: 1.1257x; 1.0557x over previous
#include <cuda_runtime.h>
#include <cuda_fp16.h>
#include <cstdint>

#define NN   100000
#define NE   1600000
#define D    128
#define DOUT 64
#define MT   128
#define NBLK ((NN + MT - 1) / MT)     // 782
#define SCANB ((NN + 255) / 256)      // 391

// ---------------- scratch ----------------
__device__ __align__(16) float g_bufA[NN * D];
__device__ __align__(16) float g_bufC[NN * D];
__device__ __align__(16) uint32_t g_hi[NN * (D / 2)];
__device__ __align__(16) uint32_t g_lo[NN * (D / 2)];
__device__ __align__(16) float g_stats2[4 * 256];  // per-stats-GEMM: [sum(128), sumsq(128)]
__device__ int g_is64;
__device__ int g_deg[NN];
__device__ int g_off[NN];
__device__ int g_cur[NN];
__device__ int g_csr[NE];
__device__ int g_bsum[512];
__device__ __align__(16) __half g_wf[8 * D * D];   // fp16 RN weights, transposed [m][n][k]

__device__ __forceinline__ uint32_t pack2h(__half a, __half b) {
    return (uint32_t)__half_as_ushort(a) | ((uint32_t)__half_as_ushort(b) << 16);
}
// fp16 two-term split: x = hi + lo with |lo| <= ulp(hi)/2  (A exact to ~2^-21)
__device__ __forceinline__ void split2(float x, float y, uint32_t& h, uint32_t& l) {
    __half hx = __float2half(x), hy = __float2half(y);
    h = pack2h(hx, hy);
    l = pack2h(__float2half(x - __half2float(hx)),
               __float2half(y - __half2float(hy)));
}

#define MMA_F16(c, a, b0_, b1_) \
    asm volatile("mma.sync.aligned.m16n8k16.row.col.f32.f16.f16.f32 " \
        "{%0,%1,%2,%3}, {%4,%5,%6,%7}, {%8,%9}, {%0,%1,%2,%3};" \
        : "+f"((c)[0]), "+f"((c)[1]), "+f"((c)[2]), "+f"((c)[3]) \
        : "r"((a)[0]), "r"((a)[1]), "r"((a)[2]), "r"((a)[3]), "r"(b0_), "r"(b1_))

// ---------------- init: zero deg + detect dtype + zero stats slots ----------------
__global__ void init_kernel(const void* ei) {
    if (blockIdx.x < SCANB) {
        int i = blockIdx.x * 256 + threadIdx.x;
        if (i < NN) g_deg[i] = 0;
    } else {
        const long long* p = (const long long*)ei;
        long long v = p[threadIdx.x];
        int ok = (v >= 0 && v < NN);
        ok = __syncthreads_and(ok);
        if (threadIdx.x == 0) g_is64 = ok;
        ((float4*)g_stats2)[threadIdx.x] = make_float4(0.f, 0.f, 0.f, 0.f);
    }
}

// transpose + fp16-round all 8 weight matrices: g_wf[m][n][k]
__global__ void prep_w(const float* __restrict__ W1, const float* __restrict__ W2,
                       const float* __restrict__ fW1, const float* __restrict__ fW2) {
    int m = blockIdx.y;
    const float* src;
    int ncols;
    if (m < 3)       { src = W1 + m * D * D;       ncols = D; }
    else if (m < 6)  { src = W2 + (m - 3) * D * D; ncols = D; }
    else if (m == 6) { src = fW1;                  ncols = D; }
    else             { src = fW2;                  ncols = DOUT; }
    int idx = blockIdx.x * 256 + threadIdx.x;
    if (idx >= ncols * D) return;
    int n = idx / D, k = idx % D;
    float v = __ldg(src + k * ncols + n);
    g_wf[m * D * D + idx] = __float2half(v);
}

// histogram of dst, 2 edges per thread (128-bit index loads)
__global__ void hist_kernel(const void* ei) {
    int e = (blockIdx.x * 256 + threadIdx.x) * 2;
    if (e >= NE) return;
    int d0, d1;
    if (g_is64) {
        longlong2 p = __ldg((const longlong2*)((const long long*)ei + NE) + (e >> 1));
        d0 = (int)p.x; d1 = (int)p.y;
    } else {
        int2 p = __ldg((const int2*)((const int*)ei + NE) + (e >> 1));
        d0 = p.x; d1 = p.y;
    }
    atomicAdd(&g_deg[d0], 1);
    atomicAdd(&g_deg[d1], 1);
}
__global__ void scan1_kernel() {
    __shared__ int s[256];
    int i = blockIdx.x * 256 + threadIdx.x;
    int v = (i < NN) ? g_deg[i] : 0;
    s[threadIdx.x] = v;
    __syncthreads();
    for (int o = 1; o < 256; o <<= 1) {
        int t = (threadIdx.x >= o) ? s[threadIdx.x - o] : 0;
        __syncthreads();
        s[threadIdx.x] += t;
        __syncthreads();
    }
    if (i < NN) g_off[i] = s[threadIdx.x];
    if (threadIdx.x == 255) g_bsum[blockIdx.x] = s[255];
}
__global__ void scan2_kernel() {
    __shared__ int s[512];
    int v = (threadIdx.x < SCANB) ? g_bsum[threadIdx.x] : 0;
    s[threadIdx.x] = v;
    __syncthreads();
    for (int o = 1; o < 512; o <<= 1) {
        int t = (threadIdx.x >= o) ? s[threadIdx.x - o] : 0;
        __syncthreads();
        s[threadIdx.x] += t;
        __syncthreads();
    }
    g_bsum[threadIdx.x] = s[threadIdx.x] - v;
}
__global__ void scan3_kernel() {
    int i = blockIdx.x * 256 + threadIdx.x;
    if (i >= NN) return;
    int e = g_off[i] - g_deg[i] + g_bsum[blockIdx.x];
    g_off[i] = e;
    g_cur[i] = e;
}
// CSR fill, 2 edges per thread
__global__ void fill_kernel(const void* ei) {
    int e = (blockIdx.x * 256 + threadIdx.x) * 2;
    if (e >= NE) return;
    int s0, s1, d0, d1;
    if (g_is64) {
        const long long* p = (const long long*)ei;
        longlong2 sp = __ldg((const longlong2*)p + (e >> 1));
        longlong2 dp = __ldg((const longlong2*)(p + NE) + (e >> 1));
        s0 = (int)sp.x; s1 = (int)sp.y; d0 = (int)dp.x; d1 = (int)dp.y;
    } else {
        const int* p = (const int*)ei;
        int2 sp = __ldg((const int2*)p + (e >> 1));
        int2 dp = __ldg((const int2*)(p + NE) + (e >> 1));
        s0 = sp.x; s1 = sp.y; d0 = dp.x; d1 = dp.y;
    }
    g_csr[atomicAdd(&g_cur[d0], 1)] = s0;
    g_csr[atomicAdd(&g_cur[d1], 1)] = s1;
}

// gather h[w] = x[w] + sum_j x[csr[j]]  -> fp16 hi/lo split, one warp per node
__global__ __launch_bounds__(256)
void gather_bf16_kernel(const float* __restrict__ x,
                        uint32_t* __restrict__ hi, uint32_t* __restrict__ lo) {
    int w = (blockIdx.x * 256 + threadIdx.x) >> 5;
    int lane = threadIdx.x & 31;
    if (w >= NN) return;
    const float4* xb = (const float4*)x;
    float4 acc = __ldg(xb + (size_t)w * 32 + lane);
    int i = g_off[w];
    int end = i + g_deg[w];
    for (; i + 4 <= end; i += 4) {
        int s0 = __ldg(g_csr + i),     s1 = __ldg(g_csr + i + 1);
        int s2 = __ldg(g_csr + i + 2), s3 = __ldg(g_csr + i + 3);
        float4 v0 = __ldg(xb + (size_t)s0 * 32 + lane);
        float4 v1 = __ldg(xb + (size_t)s1 * 32 + lane);
        float4 v2 = __ldg(xb + (size_t)s2 * 32 + lane);
        float4 v3 = __ldg(xb + (size_t)s3 * 32 + lane);
        acc.x += (v0.x + v1.x) + (v2.x + v3.x);
        acc.y += (v0.y + v1.y) + (v2.y + v3.y);
        acc.z += (v0.z + v1.z) + (v2.z + v3.z);
        acc.w += (v0.w + v1.w) + (v2.w + v3.w);
    }
    for (; i < end; ++i) {
        int s = __ldg(g_csr + i);
        float4 v = __ldg(xb + (size_t)s * 32 + lane);
        acc.x += v.x; acc.y += v.y; acc.z += v.z; acc.w += v.w;
    }
    uint32_t h0, l0, h1, l1;
    split2(acc.x, acc.y, h0, l0);
    split2(acc.z, acc.w, h1, l1);
    ((uint2*)hi)[(size_t)w * 32 + lane] = make_uint2(h0, h1);
    ((uint2*)lo)[(size_t)w * 32 + lane] = make_uint2(l0, l1);
}

// conv: fp32 -> fp16 hi/lo with BN+ReLU; scale/shift computed per-BLOCK in smem
__global__ __launch_bounds__(256)
void conv_split_bn_kernel(const float* __restrict__ C,
                          uint32_t* __restrict__ hi, uint32_t* __restrict__ lo,
                          const float* __restrict__ stats,
                          const float* __restrict__ gamma,
                          const float* __restrict__ beta) {
    __shared__ float sc_s[128], sh_s[128];
    int tid = threadIdx.x;
    if (tid < 128) {
        float mu  = stats[tid] * (1.0f / NN);
        float var = stats[128 + tid] * (1.0f / NN) - mu * mu;
        float sc  = __ldg(gamma + tid) * rsqrtf(var + 1e-5f);
        sc_s[tid] = sc;
        sh_s[tid] = __ldg(beta + tid) - mu * sc;
    }
    __syncthreads();
    int i = blockIdx.x * 256 + tid;
    if (i >= NN * 32) return;
    float4 v = __ldg((const float4*)C + i);
    int k = (i & 31) * 4;
    float4 sc = *(const float4*)(sc_s + k);
    float4 sh = *(const float4*)(sh_s + k);
    v.x = fmaxf(fmaf(v.x, sc.x, sh.x), 0.f);
    v.y = fmaxf(fmaf(v.y, sc.y, sh.y), 0.f);
    v.z = fmaxf(fmaf(v.z, sc.z, sh.z), 0.f);
    v.w = fmaxf(fmaf(v.w, sc.w, sh.w), 0.f);
    uint32_t h0, l0, h1, l1;
    split2(v.x, v.y, h0, l0);
    split2(v.z, v.w, h1, l1);
    ((uint2*)hi)[i] = make_uint2(h0, h1);
    ((uint2*)lo)[i] = make_uint2(l0, l1);
}

// ---------------- HMMA GEMM: Out = (Ah + Al) @ Wf^T + bias (fp16, 2 MMAs/step) ----
// STATS: fused column sum/sumsq of Out into stats[0:256) (shfl-reduced epilogue).
// EMIT:  0 = store fp32 Out; 1 = store fp16 hi/lo split to Ohi/Olo (no aliasing, host-guaranteed).
template <int NOUT, bool RELU, bool STATS, int EMIT>
__global__ __launch_bounds__(256, 2)
void mma_gemm(const uint32_t* __restrict__ Ahi, const uint32_t* __restrict__ Alo,
              const uint32_t* __restrict__ Wf,
              const float* __restrict__ bias, float* __restrict__ Out,
              uint32_t* __restrict__ Ohi, uint32_t* __restrict__ Olo,
              float* __restrict__ stats) {
    constexpr int WM = (NOUT == 128) ? 4 : 8;   // warps along m
    constexpr int MF = 128 / (WM * 16);         // m16 frags per warp
    constexpr int RS = 68;                      // smem row stride (u32): conflict-free, RS%4==0
    extern __shared__ uint32_t ws[];
    uint32_t* wf_s = ws;
    __shared__ float ssum[128], ssq[128];

    int tid = threadIdx.x;
    // 128-bit W staging
    for (int i = tid; i < NOUT * 16; i += 256) {
        int n = i >> 4, kw4 = i & 15;
        uint4 vh = __ldg((const uint4*)Wf + i);
        *(uint4*)(wf_s + n * RS + kw4 * 4) = vh;
    }
    if (STATS && tid < 128) { ssum[tid] = 0.f; ssq[tid] = 0.f; }
    __syncthreads();

    int wid = tid >> 5, lane = tid & 31;
    int g = lane >> 2, tig = lane & 3;
    int mwid = wid % WM, nwid = wid / WM;
    int n0 = nwid * 64;
    int mbase = blockIdx.x * MT + mwid * (MF * 16);

    float acc[MF][8][4];
#pragma unroll
    for (int mf = 0; mf < MF; ++mf)
#pragma unroll
        for (int nf = 0; nf < 8; ++nf)
#pragma unroll
            for (int c = 0; c < 4; ++c) acc[mf][nf][c] = 0.f;

    for (int ks = 0; ks < 8; ++ks) {
        uint32_t ah[MF][4], al[MF][4];
#pragma unroll
        for (int mf = 0; mf < MF; ++mf) {
            int r0 = mbase + mf * 16 + g;
            int r1 = r0 + 8;
            int o = ks * 8 + tig;
            bool v0 = r0 < NN, v1 = r1 < NN;
            size_t p0 = (size_t)r0 * 64 + o, p1 = (size_t)r1 * 64 + o;
            ah[mf][0] = v0 ? __ldg(Ahi + p0) : 0u;
            ah[mf][1] = v1 ? __ldg(Ahi + p1) : 0u;
            ah[mf][2] = v0 ? __ldg(Ahi + p0 + 4) : 0u;
            ah[mf][3] = v1 ? __ldg(Ahi + p1 + 4) : 0u;
            al[mf][0] = v0 ? __ldg(Alo + p0) : 0u;
            al[mf][1] = v1 ? __ldg(Alo + p1) : 0u;
            al[mf][2] = v0 ? __ldg(Alo + p0 + 4) : 0u;
            al[mf][3] = v1 ? __ldg(Alo + p1 + 4) : 0u;
        }
#pragma unroll
        for (int nf = 0; nf < 8; ++nf) {
            int bo = (n0 + nf * 8 + g) * RS + ks * 8 + tig;
            uint32_t b0 = wf_s[bo], b1 = wf_s[bo + 4];
#pragma unroll
            for (int mf = 0; mf < MF; ++mf) {
                MMA_F16(acc[mf][nf], ah[mf], b0, b1);
                MMA_F16(acc[mf][nf], al[mf], b0, b1);
            }
        }
    }

#pragma unroll
    for (int nf = 0; nf < 8; ++nf) {
        int col = n0 + nf * 8 + tig * 2;
        float2 b = *(const float2*)(bias + col);
        float s0 = 0.f, s1 = 0.f, q0 = 0.f, q1 = 0.f;
#pragma unroll
        for (int mf = 0; mf < MF; ++mf) {
            int r0 = mbase + mf * 16 + g;
            int r1 = r0 + 8;
            float c0 = acc[mf][nf][0] + b.x, c1 = acc[mf][nf][1] + b.y;
            float c2 = acc[mf][nf][2] + b.x, c3 = acc[mf][nf][3] + b.y;
            if (RELU) {
                c0 = fmaxf(c0, 0.f); c1 = fmaxf(c1, 0.f);
                c2 = fmaxf(c2, 0.f); c3 = fmaxf(c3, 0.f);
            }
            if (r0 < NN) {
                if (EMIT) {
                    uint32_t hh, ll;
                    split2(c0, c1, hh, ll);
                    Ohi[(size_t)r0 * 64 + col / 2] = hh;
                    Olo[(size_t)r0 * 64 + col / 2] = ll;
                } else {
                    *(float2*)(Out + (size_t)r0 * NOUT + col) = make_float2(c0, c1);
                }
                if (STATS) { s0 += c0; s1 += c1; q0 += c0 * c0; q1 += c1 * c1; }
            }
            if (r1 < NN) {
                if (EMIT) {
                    uint32_t hh, ll;
                    split2(c2, c3, hh, ll);
                    Ohi[(size_t)r1 * 64 + col / 2] = hh;
                    Olo[(size_t)r1 * 64 + col / 2] = ll;
                } else {
                    *(float2*)(Out + (size_t)r1 * NOUT + col) = make_float2(c2, c3);
                }
                if (STATS) { s0 += c2; s1 += c3; q0 += c2 * c2; q1 += c3 * c3; }
            }
        }
        if (STATS) {
#pragma unroll
            for (int o = 4; o < 32; o <<= 1) {
                s0 += __shfl_xor_sync(0xFFFFFFFFu, s0, o);
                s1 += __shfl_xor_sync(0xFFFFFFFFu, s1, o);
                q0 += __shfl_xor_sync(0xFFFFFFFFu, q0, o);
                q1 += __shfl_xor_sync(0xFFFFFFFFu, q1, o);
            }
            if (lane < 4) {
                atomicAdd(&ssum[col], s0);
                atomicAdd(&ssum[col + 1], s1);
                atomicAdd(&ssq[col], q0);
                atomicAdd(&ssq[col + 1], q1);
            }
        }
    }
    if (STATS) {
        __syncthreads();
        if (tid < 128) {
            atomicAdd(&stats[tid], ssum[tid]);
            atomicAdd(&stats[128 + tid], ssq[tid]);
        }
    }
}

// ---------------- host ----------------
extern "C" void kernel_launch(void* const* d_in, const int* in_sizes, int n_in,
                              void* d_out, int out_size) {
    const float* x    = (const float*)d_in[0];
    const void*  ei   = d_in[1];
    const float* W1   = (const float*)d_in[2];
    const float* b1   = (const float*)d_in[3];
    const float* g1   = (const float*)d_in[4];
    const float* be1  = (const float*)d_in[5];
    const float* W2   = (const float*)d_in[6];
    const float* b2   = (const float*)d_in[7];
    const float* fW1  = (const float*)d_in[8];
    const float* fb1  = (const float*)d_in[9];
    const float* fg1  = (const float*)d_in[10];
    const float* fbe1 = (const float*)d_in[11];
    const float* fW2  = (const float*)d_in[12];
    const float* fb2  = (const float*)d_in[13];
    float* out = (float*)d_out;

    float *A, *C, *st;
    uint32_t *hi, *lo, *wf;
    cudaGetSymbolAddress((void**)&A, g_bufA);
    cudaGetSymbolAddress((void**)&C, g_bufC);
    cudaGetSymbolAddress((void**)&st, g_stats2);
    cudaGetSymbolAddress((void**)&hi, g_hi);
    cudaGetSymbolAddress((void**)&lo, g_lo);
    cudaGetSymbolAddress((void**)&wf, g_wf);
    uint32_t* Chi = (uint32_t*)C;                    // layer-3 EMIT hi (C is dead then)
    uint32_t* Clo = (uint32_t*)C + (size_t)NN * 64;  // layer-3 EMIT lo

    const int SMA = 128 * 68 * 4;   // 34816 B
    const int SMB = 64 * 68 * 4;    // 17408 B
    cudaFuncSetAttribute(mma_gemm<128, false, true, 0>,
                         cudaFuncAttributeMaxDynamicSharedMemorySize, SMA);
    cudaFuncSetAttribute(mma_gemm<128, true, false, 0>,
                         cudaFuncAttributeMaxDynamicSharedMemorySize, SMA);
    cudaFuncSetAttribute(mma_gemm<128, true, false, 1>,
                         cudaFuncAttributeMaxDynamicSharedMemorySize, SMA);
    cudaFuncSetAttribute(mma_gemm<64, false, false, 0>,
                         cudaFuncAttributeMaxDynamicSharedMemorySize, SMB);

    init_kernel<<<SCANB + 1, 256>>>(ei);
    prep_w<<<dim3(64, 8), 256>>>(W1, W2, fW1, fW2);
    hist_kernel<<<NE / 512, 256>>>(ei);
    scan1_kernel<<<SCANB, 256>>>();
    scan2_kernel<<<1, 512>>>();
    scan3_kernel<<<SCANB, 256>>>();
    fill_kernel<<<NE / 512, 256>>>(ei);

    const int gblocks = (NN * 32 + 255) / 256;   // 12500
    const int cblocks = (NN * 32 + 255) / 256;

    const float* cur = x;
    for (int l = 0; l < 3; ++l) {
        float* slot = st + l * 256;
        gather_bf16_kernel<<<gblocks, 256>>>(cur, hi, lo);
        mma_gemm<128, false, true, 0><<<NBLK, 256, SMA>>>(
            hi, lo, wf + (size_t)l * D * 64, b1 + l * D, C,
            nullptr, nullptr, slot);
        conv_split_bn_kernel<<<cblocks, 256>>>(C, hi, lo, slot, g1 + l * D, be1 + l * D);
        if (l < 2) {
            mma_gemm<128, true, false, 0><<<NBLK, 256, SMA>>>(
                hi, lo, wf + (size_t)(3 + l) * D * 64,
                b2 + l * D, A, nullptr, nullptr, nullptr);
            cur = A;
        } else {
            // layer-3 GEMM2: emit fp16 hi/lo into g_bufC's storage (no aliasing)
            mma_gemm<128, true, false, 1><<<NBLK, 256, SMA>>>(
                hi, lo, wf + (size_t)(3 + l) * D * 64,
                b2 + l * D, nullptr, Chi, Clo, nullptr);
        }
    }
    // final MLP: read Chi/Clo, write fp32 to A (dead), conv -> g_hi/g_lo, last GEMM -> out
    mma_gemm<128, false, true, 0><<<NBLK, 256, SMA>>>(
        Chi, Clo, wf + (size_t)6 * D * 64, fb1, A,
        nullptr, nullptr, st + 3 * 256);
    conv_split_bn_kernel<<<cblocks, 256>>>(A, hi, lo, st + 3 * 256, fg1, fbe1);
    mma_gemm<64, false, false, 0><<<NBLK, 256, SMB>>>(
        hi, lo, wf + (size_t)7 * D * 64, fb2, out,
        nullptr, nullptr, nullptr);
}